// round 13
// baseline (speedup 1.0000x reference)
#include <cuda_runtime.h>
#include <cuda_bf16.h>
#include <cstdint>

#define RES   1024
#define FEAT  12
#define NCB   32
#define HIMG  1080
#define WIMG  1920
#define NPIX  (HIMG*WIMG)       // 2,073,600 = 4050 * 512
#define NT    256
#define PIX_PER_BLOCK 512

// ---- dynamic shared layout (bytes) ----
#define SH_H      0                         // 8 warps * 32 rows * 36 floats = 36864
#define SH_L1P    (SH_H + 8*32*36*4)        // 32*33 floats = 4224
#define SH_W2HI   (SH_L1P + 32*33*4)        // 32*40 floats = 5120
#define SH_W2LO   (SH_W2HI + 32*40*4)       // 5120
#define SH_W3     (SH_W2LO + 32*40*4)       // 3*32 floats = 384
#define SH_B2     (SH_W3 + 3*32*4)          // 128
#define SH_IDX    (SH_B2 + 32*4)            // 512 ints = 2048
#define SH_CNT    (SH_IDX + 512*4)          // 4 (+pad)
#define SMEM_TOTAL (SH_CNT + 16)

struct Consts {
    float W1d[3*32];    // W1 rows 12..14, [r][j]
    float L1P[32*32];   // B1 + W1[0:12]^T cb[c], [c][j]
    float W2[32*32];    // [k][j]
    float B2[32];
    float W3[32*3];     // [k][c]
    float B3[3];
    float pad;
    float CB[NCB*FEAT];
    float C2[NCB];
};
__device__ Consts g_stage;
__constant__ Consts cC;

__global__ void setup_kernel(const float* __restrict__ W1, const float* __restrict__ b1,
                             const float* __restrict__ W2, const float* __restrict__ b2,
                             const float* __restrict__ W3, const float* __restrict__ b3,
                             const float* __restrict__ cbk)
{
    const int t = threadIdx.x;     // 1024 threads
    if (t == 0) g_stage.pad = 0.f;
    if (t < 96)  g_stage.W1d[t] = W1[12*32 + t];
    {
        const int c = t >> 5, j = t & 31;
        float a = b1[j];
        #pragma unroll
        for (int k = 0; k < FEAT; k++) a += cbk[c*FEAT + k] * W1[k*32 + j];
        g_stage.L1P[t] = a;
    }
    g_stage.W2[t] = W2[t];
    if (t < 32)  g_stage.B2[t] = b2[t];
    if (t < 96)  g_stage.W3[t] = W3[t];
    if (t < 3)   g_stage.B3[t] = b3[t];
    if (t < NCB*FEAT) g_stage.CB[t] = cbk[t];
    if (t < NCB) {
        float a = 0.f;
        #pragma unroll
        for (int k = 0; k < FEAT; k++) { float v = cbk[t*FEAT + k]; a += v*v; }
        g_stage.C2[t] = a;
    }
}

__device__ __forceinline__ void load12(const float* __restrict__ p, float* dst) {
    float4 a = *(const float4*)(p);
    float4 b = *(const float4*)(p + 4);
    float4 c = *(const float4*)(p + 8);
    dst[0]=a.x; dst[1]=a.y; dst[2]=a.z;  dst[3]=a.w;
    dst[4]=b.x; dst[5]=b.y; dst[6]=b.z;  dst[7]=b.w;
    dst[8]=c.x; dst[9]=c.y; dst[10]=c.z; dst[11]=c.w;
}

__device__ __forceinline__ uint32_t f2tf32(float a) {
    uint32_t r; asm("cvt.rna.tf32.f32 %0, %1;" : "=r"(r) : "f"(a)); return r;
}

__device__ __forceinline__ void mma_tf32(float& d0, float& d1, float& d2, float& d3,
                                         uint32_t a0, uint32_t a1, uint32_t a2, uint32_t a3,
                                         uint32_t b0, uint32_t b1)
{
    asm volatile("mma.sync.aligned.m16n8k8.row.col.f32.tf32.tf32.f32 "
                 "{%0,%1,%2,%3}, {%4,%5,%6,%7}, {%8,%9}, {%0,%1,%2,%3};"
                 : "+f"(d0), "+f"(d1), "+f"(d2), "+f"(d3)
                 : "r"(a0), "r"(a1), "r"(a2), "r"(a3), "r"(b0), "r"(b1));
}

__global__ __launch_bounds__(NT)
void sky_kernel(const float* __restrict__ rays,
                const int* __restrict__ mask,
                const float* __restrict__ cube,
                float* __restrict__ out)
{
    extern __shared__ char dyn[];
    float* sH   = (float*)(dyn + SH_H);     // per-warp 32x36 tiles
    float* sL1P = (float*)(dyn + SH_L1P);   // stride 33
    float* sW2h = (float*)(dyn + SH_W2HI);  // [k][n] stride 40, tf32 hi
    float* sW2l = (float*)(dyn + SH_W2LO);  // tf32 lo
    float* sW3  = (float*)(dyn + SH_W3);    // [c][k], c*32+k
    float* sB2  = (float*)(dyn + SH_B2);
    int*   sIdx = (int*)(dyn + SH_IDX);
    int*   sCnt = (int*)(dyn + SH_CNT);

    const int tid    = threadIdx.x;
    const int lane   = tid & 31;
    const int warpId = tid >> 5;
    const int g = lane >> 2, r = lane & 3;

    // ---- block init ----
    for (int j = tid; j < 32*32; j += NT) sL1P[(j >> 5)*33 + (j & 31)] = cC.L1P[j];
    for (int t = tid; t < 1024; t += NT) {
        const float w = cC.W2[t];
        const uint32_t hb = f2tf32(w);
        const float hf = __uint_as_float(hb);
        const int k = t >> 5, n = t & 31;
        sW2h[k*40 + n] = hf;
        sW2l[k*40 + n] = __uint_as_float(f2tf32(w - hf));
    }
    if (tid < 96) { const int k = tid / 3, c = tid % 3; sW3[c*32 + k] = cC.W3[tid]; }
    if (tid < 32) sB2[tid] = cC.B2[tid];
    if (tid == 0) sCnt[0] = 0;
    __syncthreads();

    // ---- phase 1: block-local compaction over 512 pixels + zero fills ----
    const int base = blockIdx.x * PIX_PER_BLOCK;
    #pragma unroll
    for (int rr = 0; rr < PIX_PER_BLOCK / NT; rr++) {
        const int pix = base + rr * NT + tid;
        const bool active = (mask[pix] != 0);
        if (!active) {
            out[pix]          = 0.f;
            out[NPIX + pix]   = 0.f;
            out[2*NPIX + pix] = 0.f;
        }
        const unsigned bal = __ballot_sync(0xFFFFFFFFu, active);
        int wbase = 0;
        if (lane == 0) wbase = atomicAdd(sCnt, __popc(bal));
        wbase = __shfl_sync(0xFFFFFFFFu, wbase, 0);
        if (active) sIdx[wbase + __popc(bal & ((1u << lane) - 1u))] = rr * NT + tid;
    }
    __syncthreads();
    const int cnt = sCnt[0];

    float* sHw = sH + warpId * (32*36);
    const int iters = (cnt + NT - 1) / NT;

    for (int it = 0; it < iters; it++) {
        const int rowBase = it * NT + warpId * 32;   // compacted idx of this warp's row 0
        if (rowBase >= cnt) break;
        const int idx = rowBase + lane;
        const bool act = (idx < cnt);

        float h[32];
        if (act) {
            const int li  = sIdx[idx];
            const int pix = base + li;

            const float x = rays[3*pix+0], y = rays[3*pix+1], z = rays[3*pix+2];
            const float ax = fabsf(x), ay = fabsf(y), az = fabsf(z);
            const bool is_x = (ax >= ay) && (ax >= az);
            const bool is_y = (!is_x) && (ay >= az);

            int face; float ma, u, v;
            if (is_x)      { face = (x >= 0.f) ? 0 : 1; ma = ax; u = (x >= 0.f) ? -z : z; v = -y; }
            else if (is_y) { face = (y >= 0.f) ? 2 : 3; ma = ay; u = x; v = (y >= 0.f) ? z : -z; }
            else           { face = (z >= 0.f) ? 4 : 5; ma = az; u = (z >= 0.f) ? x : -x; v = -y; }

            const float inv = __fdividef(1.f, ma + 1e-9f);
            const float sc = (u*inv + 1.f) * 0.5f * (float)RES - 0.5f;
            const float tc = (v*inv + 1.f) * 0.5f * (float)RES - 0.5f;
            const float fs = floorf(sc), ft = floorf(tc);
            const float fx = sc - fs, fy = tc - ft;
            int x0 = (int)fs; x0 = max(0, min(x0, RES-1));
            const int x1 = min(x0+1, RES-1);
            int y0 = (int)ft; y0 = max(0, min(y0, RES-1));
            const int y1 = min(y0+1, RES-1);

            const float* __restrict__ fb = cube + (size_t)face * (size_t)(RES*RES*FEAT);

            float feat[FEAT], tmp[FEAT], bot[FEAT];
            load12(fb + ((size_t)y0*RES + x0)*FEAT, feat);
            load12(fb + ((size_t)y0*RES + x1)*FEAT, tmp);
            #pragma unroll
            for (int k = 0; k < FEAT; k++) feat[k] = feat[k]*(1.f-fx) + tmp[k]*fx;
            load12(fb + ((size_t)y1*RES + x0)*FEAT, bot);
            load12(fb + ((size_t)y1*RES + x1)*FEAT, tmp);
            #pragma unroll
            for (int k = 0; k < FEAT; k++) bot[k] = bot[k]*(1.f-fx) + tmp[k]*fx;
            #pragma unroll
            for (int k = 0; k < FEAT; k++) feat[k] = feat[k]*(1.f-fy) + bot[k]*fy;

            int best = 0;
            float bestd = 3.4e38f;
            #pragma unroll 4
            for (int c = 0; c < NCB; c++) {
                float dot = 0.f;
                #pragma unroll
                for (int k = 0; k < FEAT; k++) dot += feat[k]*cC.CB[c*FEAT + k];
                const float d2 = cC.C2[c] - 2.f*dot;
                if (d2 < bestd) { bestd = d2; best = c; }
            }

            const float* __restrict__ rowp = sL1P + best*33;
            #pragma unroll
            for (int j = 0; j < 32; j++) {
                float a = rowp[j];
                a += x * cC.W1d[j];
                a += y * cC.W1d[32 + j];
                a += z * cC.W1d[64 + j];
                h[j] = fmaxf(a, 0.f);
            }
        } else {
            #pragma unroll
            for (int j = 0; j < 32; j++) h[j] = 0.f;
        }

        // stage H tile (lane = row)
        #pragma unroll
        for (int j = 0; j < 8; j++)
            *(float4*)&sHw[lane*36 + 4*j] = make_float4(h[4*j], h[4*j+1], h[4*j+2], h[4*j+3]);
        __syncwarp();

        // D fragments, bias-initialized: c0=B2[8nt+2r], c1=+1, c2/c3 same cols
        float d[2][4][4];
        #pragma unroll
        for (int nt = 0; nt < 4; nt++) {
            const float2 b = *(const float2*)&sB2[8*nt + 2*r];
            #pragma unroll
            for (int mt = 0; mt < 2; mt++) {
                d[mt][nt][0] = b.x; d[mt][nt][1] = b.y;
                d[mt][nt][2] = b.x; d[mt][nt][3] = b.y;
            }
        }

        // 3xTF32 GEMM: 32x32x32
        #pragma unroll
        for (int kt = 0; kt < 4; kt++) {
            uint32_t ahi[2][4], alo[2][4];
            #pragma unroll
            for (int mt = 0; mt < 2; mt++) {
                const float a0 = sHw[(g + 16*mt)*36     + kt*8 + r];
                const float a1 = sHw[(g + 8 + 16*mt)*36 + kt*8 + r];
                const float a2 = sHw[(g + 16*mt)*36     + kt*8 + r + 4];
                const float a3 = sHw[(g + 8 + 16*mt)*36 + kt*8 + r + 4];
                ahi[mt][0] = f2tf32(a0); alo[mt][0] = f2tf32(a0 - __uint_as_float(ahi[mt][0]));
                ahi[mt][1] = f2tf32(a1); alo[mt][1] = f2tf32(a1 - __uint_as_float(ahi[mt][1]));
                ahi[mt][2] = f2tf32(a2); alo[mt][2] = f2tf32(a2 - __uint_as_float(ahi[mt][2]));
                ahi[mt][3] = f2tf32(a3); alo[mt][3] = f2tf32(a3 - __uint_as_float(ahi[mt][3]));
            }
            #pragma unroll
            for (int nt = 0; nt < 4; nt++) {
                const uint32_t bh0 = __float_as_uint(sW2h[(kt*8 + r)*40     + nt*8 + g]);
                const uint32_t bh1 = __float_as_uint(sW2h[(kt*8 + r + 4)*40 + nt*8 + g]);
                const uint32_t bl0 = __float_as_uint(sW2l[(kt*8 + r)*40     + nt*8 + g]);
                const uint32_t bl1 = __float_as_uint(sW2l[(kt*8 + r + 4)*40 + nt*8 + g]);
                #pragma unroll
                for (int mt = 0; mt < 2; mt++) {
                    mma_tf32(d[mt][nt][0], d[mt][nt][1], d[mt][nt][2], d[mt][nt][3],
                             ahi[mt][0], ahi[mt][1], ahi[mt][2], ahi[mt][3], bh0, bh1);
                    mma_tf32(d[mt][nt][0], d[mt][nt][1], d[mt][nt][2], d[mt][nt][3],
                             ahi[mt][0], ahi[mt][1], ahi[mt][2], ahi[mt][3], bl0, bl1);
                    mma_tf32(d[mt][nt][0], d[mt][nt][1], d[mt][nt][2], d[mt][nt][3],
                             alo[mt][0], alo[mt][1], alo[mt][2], alo[mt][3], bh0, bh1);
                }
            }
        }
        __syncwarp();   // done reading sHw; safe to overwrite next iteration

        // layer 3 on fragments: relu, per-lane partial dot over its 8 cols
        float part[4][3];
        #pragma unroll
        for (int s = 0; s < 4; s++) { part[s][0] = 0.f; part[s][1] = 0.f; part[s][2] = 0.f; }
        #pragma unroll
        for (int nt = 0; nt < 4; nt++) {
            #pragma unroll
            for (int jb = 0; jb < 2; jb++) {
                const int col = 8*nt + 2*r + jb;
                const float w0 = sW3[col], w1 = sW3[32 + col], w2 = sW3[64 + col];
                #pragma unroll
                for (int mt = 0; mt < 2; mt++) {
                    #pragma unroll
                    for (int jh = 0; jh < 2; jh++) {
                        const float hv = fmaxf(d[mt][nt][2*jh + jb], 0.f);
                        const int s = 2*mt + jh;       // pixel row = g + 8*s
                        part[s][0] += hv * w0;
                        part[s][1] += hv * w1;
                        part[s][2] += hv * w2;
                    }
                }
            }
        }
        // butterfly-reduce across the 4-lane group (r dimension)
        #pragma unroll
        for (int s = 0; s < 4; s++) {
            #pragma unroll
            for (int c = 0; c < 3; c++) {
                float v = part[s][c];
                v += __shfl_xor_sync(0xFFFFFFFFu, v, 1);
                v += __shfl_xor_sync(0xFFFFFFFFu, v, 2);
                part[s][c] = v;
            }
        }
        // lane r (<3) stores channel r for the group's 4 pixels
        if (r < 3) {
            #pragma unroll
            for (int s = 0; s < 4; s++) {
                const int ai = rowBase + g + 8*s;
                if (ai < cnt) {
                    const int pix = base + sIdx[ai];
                    const float val = part[s][r] + cC.B3[r];
                    float sg = __fdividef(1.f, 1.f + __expf(-val));
                    sg = fminf(fmaxf(sg, 0.f), 1.f);
                    out[r*NPIX + pix] = sg;
                }
            }
        }
        __syncwarp();
    }
}

extern "C" void kernel_launch(void* const* d_in, const int* in_sizes, int n_in,
                              void* d_out, int out_size)
{
    const float* rays = (const float*)d_in[0];
    const int*   mask = (const int*)d_in[1];
    const float* cube = (const float*)d_in[2];
    const float* cbk  = (const float*)d_in[3];
    const float* W1   = (const float*)d_in[4];
    const float* b1   = (const float*)d_in[5];
    const float* W2   = (const float*)d_in[6];
    const float* b2   = (const float*)d_in[7];
    const float* W3   = (const float*)d_in[8];
    const float* b3   = (const float*)d_in[9];
    float* out = (float*)d_out;

    static bool attr_set = false;
    if (!attr_set) {
        cudaFuncSetAttribute(sky_kernel, cudaFuncAttributeMaxDynamicSharedMemorySize, SMEM_TOTAL);
        attr_set = true;
    }

    setup_kernel<<<1, 1024>>>(W1, b1, W2, b2, W3, b3, cbk);

    void* stage_ptr = nullptr;
    cudaGetSymbolAddress(&stage_ptr, g_stage);
    cudaMemcpyToSymbolAsync(cC, stage_ptr, sizeof(Consts), 0, cudaMemcpyDeviceToDevice, 0);

    sky_kernel<<<NPIX / PIX_PER_BLOCK, NT, SMEM_TOTAL>>>(rays, mask, cube, out);
}

// round 14
// speedup vs baseline: 1.1992x; 1.1992x over previous
#include <cuda_runtime.h>
#include <cuda_bf16.h>

#define RES   1024
#define FEAT  12
#define NCB   32
#define HIMG  1080
#define WIMG  1920
#define NPIX  (HIMG*WIMG)       // 2,073,600 = 4050 * 512
#define NT    256
#define PIX_PER_BLOCK 512

struct Consts {
    float W1d[3*32];    // W1 rows 12..14 (direction weights), [r][j]
    float L1P[32*32];   // B1 + W1[0:12]^T cb[c], [c][j]
    float W2[32*32];    // [k][j]
    float B2[32];
    float W3[32*3];     // [k][c]
    float B3[3];
    float pad;
    float CB[NCB*FEAT];
    float C2[NCB];
};
__device__ Consts g_stage;
__constant__ Consts cC;

__global__ void setup_kernel(const float* __restrict__ W1, const float* __restrict__ b1,
                             const float* __restrict__ W2, const float* __restrict__ b2,
                             const float* __restrict__ W3, const float* __restrict__ b3,
                             const float* __restrict__ cbk)
{
    const int t = threadIdx.x;     // 1024 threads
    if (t == 0) g_stage.pad = 0.f;
    if (t < 96)  g_stage.W1d[t] = W1[12*32 + t];          // rows 12..14
    {
        const int c = t >> 5, j = t & 31;
        float a = b1[j];
        #pragma unroll
        for (int k = 0; k < FEAT; k++) a += cbk[c*FEAT + k] * W1[k*32 + j];
        g_stage.L1P[t] = a;
    }
    g_stage.W2[t] = W2[t];         // exactly 1024
    if (t < 32)  g_stage.B2[t] = b2[t];
    if (t < 96)  g_stage.W3[t] = W3[t];
    if (t < 3)   g_stage.B3[t] = b3[t];
    if (t < NCB*FEAT) g_stage.CB[t] = cbk[t];
    if (t < NCB) {
        float a = 0.f;
        #pragma unroll
        for (int k = 0; k < FEAT; k++) { float v = cbk[t*FEAT + k]; a += v*v; }
        g_stage.C2[t] = a;
    }
}

__device__ __forceinline__ void load12(const float* __restrict__ p, float* dst) {
    float4 a = *(const float4*)(p);
    float4 b = *(const float4*)(p + 4);
    float4 c = *(const float4*)(p + 8);
    dst[0]=a.x; dst[1]=a.y; dst[2]=a.z;  dst[3]=a.w;
    dst[4]=b.x; dst[5]=b.y; dst[6]=b.z;  dst[7]=b.w;
    dst[8]=c.x; dst[9]=c.y; dst[10]=c.z; dst[11]=c.w;
}

// load two adjacent texels (96B contiguous) and lerp: dst = a*(1-fx) + b*fx
__device__ __forceinline__ void load_row_lerp(const float* __restrict__ p,
                                              bool adjacent, float fx, float* dst)
{
    if (adjacent) {
        float a[12], b[12];
        float4 q0 = ((const float4*)p)[0];
        float4 q1 = ((const float4*)p)[1];
        float4 q2 = ((const float4*)p)[2];
        float4 q3 = ((const float4*)p)[3];
        float4 q4 = ((const float4*)p)[4];
        float4 q5 = ((const float4*)p)[5];
        a[0]=q0.x; a[1]=q0.y; a[2]=q0.z;  a[3]=q0.w;
        a[4]=q1.x; a[5]=q1.y; a[6]=q1.z;  a[7]=q1.w;
        a[8]=q2.x; a[9]=q2.y; a[10]=q2.z; a[11]=q2.w;
        b[0]=q3.x; b[1]=q3.y; b[2]=q3.z;  b[3]=q3.w;
        b[4]=q4.x; b[5]=q4.y; b[6]=q4.z;  b[7]=q4.w;
        b[8]=q5.x; b[9]=q5.y; b[10]=q5.z; b[11]=q5.w;
        #pragma unroll
        for (int k = 0; k < 12; k++) dst[k] = a[k]*(1.f-fx) + b[k]*fx;
    } else {
        // x1 == x0 (border): both texels identical; lerp degenerates to the texel
        load12(p, dst);
    }
}

__global__ __launch_bounds__(NT, 4)
void sky_kernel(const float* __restrict__ rays,
                const int* __restrict__ mask,
                const float* __restrict__ cube,
                float* __restrict__ out)
{
    __shared__ float sL1P[32*33];            // stride-33: conflict-free divergent row gather
    __shared__ float sOut[3][PIX_PER_BLOCK]; // staged outputs, dumped coalesced
    __shared__ int   sIdx[PIX_PER_BLOCK];
    __shared__ int   sCnt;

    const int tid  = threadIdx.x;
    const int lane = tid & 31;
    for (int j = tid; j < 32*32; j += NT) sL1P[(j >> 5)*33 + (j & 31)] = cC.L1P[j];
    if (tid == 0) sCnt = 0;
    __syncthreads();

    // ---- phase 1: block-local compaction; zeros staged to shared ----
    const int base = blockIdx.x * PIX_PER_BLOCK;
    #pragma unroll
    for (int r = 0; r < PIX_PER_BLOCK / NT; r++) {
        const int li  = r * NT + tid;
        const bool active = (mask[base + li] != 0);
        if (!active) { sOut[0][li] = 0.f; sOut[1][li] = 0.f; sOut[2][li] = 0.f; }
        const unsigned bal = __ballot_sync(0xFFFFFFFFu, active);
        int wbase = 0;
        if (lane == 0) wbase = atomicAdd(&sCnt, __popc(bal));
        wbase = __shfl_sync(0xFFFFFFFFu, wbase, 0);
        if (active) sIdx[wbase + __popc(bal & ((1u << lane) - 1u))] = li;
    }
    __syncthreads();
    const int cnt = sCnt;

    // ---- phase 2: process compacted pixels ----
    for (int i = tid; i < cnt; i += NT) {
        const int li  = sIdx[i];
        const int pix = base + li;

        const float x = rays[3*pix+0], y = rays[3*pix+1], z = rays[3*pix+2];
        const float ax = fabsf(x), ay = fabsf(y), az = fabsf(z);
        const bool is_x = (ax >= ay) && (ax >= az);
        const bool is_y = (!is_x) && (ay >= az);

        int face; float ma, u, v;
        if (is_x)      { face = (x >= 0.f) ? 0 : 1; ma = ax; u = (x >= 0.f) ? -z : z; v = -y; }
        else if (is_y) { face = (y >= 0.f) ? 2 : 3; ma = ay; u = x; v = (y >= 0.f) ? z : -z; }
        else           { face = (z >= 0.f) ? 4 : 5; ma = az; u = (z >= 0.f) ? x : -x; v = -y; }

        const float inv = __fdividef(1.f, ma + 1e-9f);
        const float sc = (u*inv + 1.f) * 0.5f * (float)RES - 0.5f;
        const float tc = (v*inv + 1.f) * 0.5f * (float)RES - 0.5f;
        const float fs = floorf(sc), ft = floorf(tc);
        const float fx = sc - fs, fy = tc - ft;
        int x0 = (int)fs; x0 = max(0, min(x0, RES-1));
        const int x1 = min(x0+1, RES-1);
        int y0 = (int)ft; y0 = max(0, min(y0, RES-1));
        const int y1 = min(y0+1, RES-1);

        const float* __restrict__ fb = cube + (size_t)face * (size_t)(RES*RES*FEAT);
        const bool adj = (x1 > x0);

        float feat[FEAT], bot[FEAT];
        load_row_lerp(fb + ((size_t)y0*RES + x0)*FEAT, adj, fx, feat);
        load_row_lerp(fb + ((size_t)y1*RES + x0)*FEAT, adj, fx, bot);
        #pragma unroll
        for (int k = 0; k < FEAT; k++) feat[k] = feat[k]*(1.f-fy) + bot[k]*fy;

        // nearest codebook: argmin_c (C2[c] - 2*dot)
        int best = 0;
        float bestd = 3.4e38f;
        #pragma unroll 4
        for (int c = 0; c < NCB; c++) {
            float dot = 0.f;
            #pragma unroll
            for (int k = 0; k < FEAT; k++) dot += feat[k]*cC.CB[c*FEAT + k];
            const float d2 = cC.C2[c] - 2.f*dot;
            if (d2 < bestd) { bestd = d2; best = c; }
        }

        // layer 1 (collapsed): relu(L1P[best] + x*W1[12] + y*W1[13] + z*W1[14])
        const float* __restrict__ rowp = sL1P + best*33;
        float h[32];
        #pragma unroll
        for (int j = 0; j < 32; j++) {
            float a = rowp[j];
            a += x * cC.W1d[j];
            a += y * cC.W1d[32 + j];
            a += z * cC.W1d[64 + j];
            h[j] = fmaxf(a, 0.f);
        }

        // layer 2: 32 -> 32, relu
        float h2[32];
        #pragma unroll
        for (int j = 0; j < 32; j++) h2[j] = cC.B2[j];
        #pragma unroll
        for (int k = 0; k < 32; k++) {
            const float iv = h[k];
            #pragma unroll
            for (int j = 0; j < 32; j++) h2[j] += iv * cC.W2[k*32 + j];
        }
        #pragma unroll
        for (int j = 0; j < 32; j++) h2[j] = fmaxf(h2[j], 0.f);

        // layer 3: 32 -> 3, sigmoid
        float r0 = cC.B3[0], r1 = cC.B3[1], r2 = cC.B3[2];
        #pragma unroll
        for (int k = 0; k < 32; k++) {
            const float iv = h2[k];
            r0 += iv * cC.W3[k*3 + 0];
            r1 += iv * cC.W3[k*3 + 1];
            r2 += iv * cC.W3[k*3 + 2];
        }
        float s0 = __fdividef(1.f, 1.f + __expf(-r0));
        float s1 = __fdividef(1.f, 1.f + __expf(-r1));
        float s2 = __fdividef(1.f, 1.f + __expf(-r2));
        sOut[0][li] = fminf(fmaxf(s0, 0.f), 1.f);
        sOut[1][li] = fminf(fmaxf(s1, 0.f), 1.f);
        sOut[2][li] = fminf(fmaxf(s2, 0.f), 1.f);
    }
    __syncthreads();

    // ---- phase 3: coalesced dump (384 float4s per block) ----
    for (int t = tid; t < 3 * (PIX_PER_BLOCK/4); t += NT) {
        const int c = t / (PIX_PER_BLOCK/4);
        const int q = t % (PIX_PER_BLOCK/4);
        ((float4*)(out + (size_t)c*NPIX + base))[q] = ((const float4*)&sOut[c][0])[q];
    }
}

extern "C" void kernel_launch(void* const* d_in, const int* in_sizes, int n_in,
                              void* d_out, int out_size)
{
    const float* rays = (const float*)d_in[0];
    const int*   mask = (const int*)d_in[1];
    const float* cube = (const float*)d_in[2];
    const float* cbk  = (const float*)d_in[3];
    const float* W1   = (const float*)d_in[4];
    const float* b1   = (const float*)d_in[5];
    const float* W2   = (const float*)d_in[6];
    const float* b2   = (const float*)d_in[7];
    const float* W3   = (const float*)d_in[8];
    const float* b3   = (const float*)d_in[9];
    float* out = (float*)d_out;

    setup_kernel<<<1, 1024>>>(W1, b1, W2, b2, W3, b3, cbk);

    void* stage_ptr = nullptr;
    cudaGetSymbolAddress(&stage_ptr, g_stage);
    cudaMemcpyToSymbolAsync(cC, stage_ptr, sizeof(Consts), 0, cudaMemcpyDeviceToDevice, 0);

    sky_kernel<<<NPIX / PIX_PER_BLOCK, NT>>>(rays, mask, cube, out);
}

// round 15
// speedup vs baseline: 1.2021x; 1.0024x over previous
#include <cuda_runtime.h>
#include <cuda_bf16.h>

#define RES   1024
#define FEAT  12
#define NCB   32
#define HIMG  1080
#define WIMG  1920
#define NPIX  (HIMG*WIMG)       // 2,073,600 = 5400 * 384
#define NT    256
#define PIX_PER_BLOCK 384       // E[active]=192 < NT: phase 2 is single-pass w.h.p.

struct Consts {
    float W1d[3*32];    // W1 rows 12..14 (direction weights), [r][j]
    float L1P[32*32];   // B1 + W1[0:12]^T cb[c], [c][j]
    float W2[32*32];    // [k][j]
    float B2[32];
    float W3[32*3];     // [k][c]
    float B3[3];
    float pad;
    float CB[NCB*FEAT];
    float C2[NCB];
};
__device__ Consts g_stage;
__constant__ Consts cC;

__global__ void setup_kernel(const float* __restrict__ W1, const float* __restrict__ b1,
                             const float* __restrict__ W2, const float* __restrict__ b2,
                             const float* __restrict__ W3, const float* __restrict__ b3,
                             const float* __restrict__ cbk)
{
    const int t = threadIdx.x;     // 1024 threads
    if (t == 0) g_stage.pad = 0.f;
    if (t < 96)  g_stage.W1d[t] = W1[12*32 + t];          // rows 12..14
    {
        const int c = t >> 5, j = t & 31;
        float a = b1[j];
        #pragma unroll
        for (int k = 0; k < FEAT; k++) a += cbk[c*FEAT + k] * W1[k*32 + j];
        g_stage.L1P[t] = a;
    }
    g_stage.W2[t] = W2[t];         // exactly 1024
    if (t < 32)  g_stage.B2[t] = b2[t];
    if (t < 96)  g_stage.W3[t] = W3[t];
    if (t < 3)   g_stage.B3[t] = b3[t];
    if (t < NCB*FEAT) g_stage.CB[t] = cbk[t];
    if (t < NCB) {
        float a = 0.f;
        #pragma unroll
        for (int k = 0; k < FEAT; k++) { float v = cbk[t*FEAT + k]; a += v*v; }
        g_stage.C2[t] = a;
    }
}

__device__ __forceinline__ void load12(const float* __restrict__ p, float* dst) {
    float4 a = *(const float4*)(p);
    float4 b = *(const float4*)(p + 4);
    float4 c = *(const float4*)(p + 8);
    dst[0]=a.x; dst[1]=a.y; dst[2]=a.z;  dst[3]=a.w;
    dst[4]=b.x; dst[5]=b.y; dst[6]=b.z;  dst[7]=b.w;
    dst[8]=c.x; dst[9]=c.y; dst[10]=c.z; dst[11]=c.w;
}

__global__ __launch_bounds__(NT, 4)
void sky_kernel(const float* __restrict__ rays,
                const int* __restrict__ mask,
                const float* __restrict__ cube,
                float* __restrict__ out)
{
    __shared__ float sL1P[32*33];     // stride-33: divergent row gather is bank-conflict-free
    __shared__ int   sIdx[PIX_PER_BLOCK];
    __shared__ int   sCnt;

    const int tid  = threadIdx.x;
    const int lane = tid & 31;
    for (int j = tid; j < 32*32; j += NT) sL1P[(j >> 5)*33 + (j & 31)] = cC.L1P[j];
    if (tid == 0) sCnt = 0;
    __syncthreads();

    // ---- phase 1: block-local compaction over 384 pixels + zero fills ----
    const int base = blockIdx.x * PIX_PER_BLOCK;
    #pragma unroll
    for (int r = 0; r < (PIX_PER_BLOCK + NT - 1) / NT; r++) {
        const int li = r * NT + tid;
        bool active = false;
        if (li < PIX_PER_BLOCK) {
            const int pix = base + li;
            active = (mask[pix] != 0);
            if (!active) {
                out[pix]          = 0.f;
                out[NPIX + pix]   = 0.f;
                out[2*NPIX + pix] = 0.f;
            }
        }
        const unsigned bal = __ballot_sync(0xFFFFFFFFu, active);
        int wbase = 0;
        if (lane == 0) wbase = atomicAdd(&sCnt, __popc(bal));
        wbase = __shfl_sync(0xFFFFFFFFu, wbase, 0);
        if (active) sIdx[wbase + __popc(bal & ((1u << lane) - 1u))] = li;
    }
    __syncthreads();
    const int cnt = sCnt;

    // ---- phase 2: process compacted pixels (single pass w.h.p.) ----
    for (int i = tid; i < cnt; i += NT) {
        const int li  = sIdx[i];
        const int pix = base + li;

        const float x = rays[3*pix+0], y = rays[3*pix+1], z = rays[3*pix+2];
        const float ax = fabsf(x), ay = fabsf(y), az = fabsf(z);
        const bool is_x = (ax >= ay) && (ax >= az);
        const bool is_y = (!is_x) && (ay >= az);

        int face; float ma, u, v;
        if (is_x)      { face = (x >= 0.f) ? 0 : 1; ma = ax; u = (x >= 0.f) ? -z : z; v = -y; }
        else if (is_y) { face = (y >= 0.f) ? 2 : 3; ma = ay; u = x; v = (y >= 0.f) ? z : -z; }
        else           { face = (z >= 0.f) ? 4 : 5; ma = az; u = (z >= 0.f) ? x : -x; v = -y; }

        const float inv = __fdividef(1.f, ma + 1e-9f);
        const float sc = (u*inv + 1.f) * 0.5f * (float)RES - 0.5f;
        const float tc = (v*inv + 1.f) * 0.5f * (float)RES - 0.5f;
        const float fs = floorf(sc), ft = floorf(tc);
        const float fx = sc - fs, fy = tc - ft;
        int x0 = (int)fs; x0 = max(0, min(x0, RES-1));
        const int x1 = min(x0+1, RES-1);
        int y0 = (int)ft; y0 = max(0, min(y0, RES-1));
        const int y1 = min(y0+1, RES-1);

        const float* __restrict__ fb = cube + (size_t)face * (size_t)(RES*RES*FEAT);

        float feat[FEAT], tmp[FEAT], bot[FEAT];
        load12(fb + ((size_t)y0*RES + x0)*FEAT, feat);
        load12(fb + ((size_t)y0*RES + x1)*FEAT, tmp);
        #pragma unroll
        for (int k = 0; k < FEAT; k++) feat[k] = feat[k]*(1.f-fx) + tmp[k]*fx;
        load12(fb + ((size_t)y1*RES + x0)*FEAT, bot);
        load12(fb + ((size_t)y1*RES + x1)*FEAT, tmp);
        #pragma unroll
        for (int k = 0; k < FEAT; k++) bot[k] = bot[k]*(1.f-fx) + tmp[k]*fx;
        #pragma unroll
        for (int k = 0; k < FEAT; k++) feat[k] = feat[k]*(1.f-fy) + bot[k]*fy;

        // nearest codebook: argmin_c (C2[c] - 2*dot)
        int best = 0;
        float bestd = 3.4e38f;
        #pragma unroll 4
        for (int c = 0; c < NCB; c++) {
            float dot = 0.f;
            #pragma unroll
            for (int k = 0; k < FEAT; k++) dot += feat[k]*cC.CB[c*FEAT + k];
            const float d2 = cC.C2[c] - 2.f*dot;
            if (d2 < bestd) { bestd = d2; best = c; }
        }

        // layer 1 (collapsed): relu(L1P[best] + x*W1[12] + y*W1[13] + z*W1[14])
        const float* __restrict__ rowp = sL1P + best*33;
        float h[32];
        #pragma unroll
        for (int j = 0; j < 32; j++) {
            float a = rowp[j];
            a += x * cC.W1d[j];
            a += y * cC.W1d[32 + j];
            a += z * cC.W1d[64 + j];
            h[j] = fmaxf(a, 0.f);
        }

        // layer 2: 32 -> 32, relu
        float h2[32];
        #pragma unroll
        for (int j = 0; j < 32; j++) h2[j] = cC.B2[j];
        #pragma unroll
        for (int k = 0; k < 32; k++) {
            const float iv = h[k];
            #pragma unroll
            for (int j = 0; j < 32; j++) h2[j] += iv * cC.W2[k*32 + j];
        }
        #pragma unroll
        for (int j = 0; j < 32; j++) h2[j] = fmaxf(h2[j], 0.f);

        // layer 3: 32 -> 3, sigmoid
        float r0 = cC.B3[0], r1 = cC.B3[1], r2 = cC.B3[2];
        #pragma unroll
        for (int k = 0; k < 32; k++) {
            const float iv = h2[k];
            r0 += iv * cC.W3[k*3 + 0];
            r1 += iv * cC.W3[k*3 + 1];
            r2 += iv * cC.W3[k*3 + 2];
        }
        float s0 = __fdividef(1.f, 1.f + __expf(-r0));
        float s1 = __fdividef(1.f, 1.f + __expf(-r1));
        float s2 = __fdividef(1.f, 1.f + __expf(-r2));
        out[pix]          = fminf(fmaxf(s0, 0.f), 1.f);
        out[NPIX + pix]   = fminf(fmaxf(s1, 0.f), 1.f);
        out[2*NPIX + pix] = fminf(fmaxf(s2, 0.f), 1.f);
    }
}

extern "C" void kernel_launch(void* const* d_in, const int* in_sizes, int n_in,
                              void* d_out, int out_size)
{
    const float* rays = (const float*)d_in[0];
    const int*   mask = (const int*)d_in[1];
    const float* cube = (const float*)d_in[2];
    const float* cbk  = (const float*)d_in[3];
    const float* W1   = (const float*)d_in[4];
    const float* b1   = (const float*)d_in[5];
    const float* W2   = (const float*)d_in[6];
    const float* b2   = (const float*)d_in[7];
    const float* W3   = (const float*)d_in[8];
    const float* b3   = (const float*)d_in[9];
    float* out = (float*)d_out;

    setup_kernel<<<1, 1024>>>(W1, b1, W2, b2, W3, b3, cbk);

    void* stage_ptr = nullptr;
    cudaGetSymbolAddress(&stage_ptr, g_stage);
    cudaMemcpyToSymbolAsync(cC, stage_ptr, sizeof(Consts), 0, cudaMemcpyDeviceToDevice, 0);

    sky_kernel<<<NPIX / PIX_PER_BLOCK, NT>>>(rays, mask, cube, out);
}